// round 5
// baseline (speedup 1.0000x reference)
#include <cuda_runtime.h>
#include <cuda_bf16.h>
#include <cstdint>

// ---------------- problem constants ----------------
#define NN      50000
#define EE      800000
#define IN_DIM  768
#define HID     256
#define OUT_DIM 128
#define BN_EPS  1e-5f
#define NORM_EPS 1e-12f

// ---------------- scratch (device globals — allocation-free) ----------------
__device__ float g_deg[NN];
__device__ float g_t[(size_t)NN * HID];     // GEMM fp32 output (gather source)
__device__ float g_a[(size_t)NN * HID];     // aggregation buffer
__device__ __nv_bfloat16 g_xhi[(size_t)NN * IN_DIM];
__device__ __nv_bfloat16 g_xlo[(size_t)NN * IN_DIM];
__device__ __nv_bfloat16 g_hhi[(size_t)NN * HID];
__device__ __nv_bfloat16 g_hlo[(size_t)NN * HID];
__device__ __nv_bfloat16 g_w1hi[HID * IN_DIM];   // transposed [N,K]
__device__ __nv_bfloat16 g_w1lo[HID * IN_DIM];
__device__ __nv_bfloat16 g_w2hi[HID * HID];
__device__ __nv_bfloat16 g_w2lo[HID * HID];
__device__ __nv_bfloat16 g_w3hi[OUT_DIM * HID];
__device__ __nv_bfloat16 g_w3lo[OUT_DIM * HID];

// ---------------- small PTX helpers ----------------
__device__ __forceinline__ void red_add_v4(float4* p, float4 v) {
    asm volatile("red.global.add.v4.f32 [%0], {%1,%2,%3,%4};"
                 :: "l"(p), "f"(v.x), "f"(v.y), "f"(v.z), "f"(v.w)
                 : "memory");
}

__device__ __forceinline__ uint32_t smem_u32(const void* p) {
    uint32_t a;
    asm("{ .reg .u64 t; cvta.to.shared.u64 t, %1; cvt.u32.u64 %0, t; }"
        : "=r"(a) : "l"(p));
    return a;
}

__device__ __forceinline__ void cp_async16(uint32_t smem, const void* g) {
    asm volatile("cp.async.cg.shared.global [%0], [%1], 16;"
                 :: "r"(smem), "l"(g) : "memory");
}
#define CP_COMMIT() asm volatile("cp.async.commit_group;" ::: "memory")

__device__ __forceinline__ void ldsm_x4(uint32_t addr, uint32_t& r0, uint32_t& r1,
                                        uint32_t& r2, uint32_t& r3) {
    asm volatile("ldmatrix.sync.aligned.m8n8.x4.shared.b16 {%0,%1,%2,%3}, [%4];"
                 : "=r"(r0), "=r"(r1), "=r"(r2), "=r"(r3) : "r"(addr));
}
__device__ __forceinline__ void ldsm_x2(uint32_t addr, uint32_t& r0, uint32_t& r1) {
    asm volatile("ldmatrix.sync.aligned.m8n8.x2.shared.b16 {%0,%1}, [%2];"
                 : "=r"(r0), "=r"(r1) : "r"(addr));
}

__device__ __forceinline__ void mma_bf16(float* c, const uint32_t* a, const uint32_t* b) {
    asm volatile(
        "mma.sync.aligned.m16n8k16.row.col.f32.bf16.bf16.f32 "
        "{%0,%1,%2,%3}, {%4,%5,%6,%7}, {%8,%9}, {%0,%1,%2,%3};"
        : "+f"(c[0]), "+f"(c[1]), "+f"(c[2]), "+f"(c[3])
        : "r"(a[0]), "r"(a[1]), "r"(a[2]), "r"(a[3]), "r"(b[0]), "r"(b[1]));
}

__device__ __forceinline__ void split2(float v, __nv_bfloat16& hi, __nv_bfloat16& lo) {
    hi = __float2bfloat16_rn(v);
    lo = __float2bfloat16_rn(v - __bfloat162float(hi));
}

// ---------------- degree / norm ----------------
__global__ void k_deg_init(float* deg, int n) {
    int i = blockIdx.x * blockDim.x + threadIdx.x;
    if (i < n) deg[i] = 1.0f;
}
__global__ void k_deg_scatter(const int* __restrict__ ei, const float* __restrict__ ew,
                              float* deg, int e) {
    int i = blockIdx.x * blockDim.x + threadIdx.x;
    if (i < e) atomicAdd(&deg[ei[e + i]], ew[i]);
}
__global__ void k_rsqrt(float* deg, int n) {
    int i = blockIdx.x * blockDim.x + threadIdx.x;
    if (i < n) { float d = deg[i]; deg[i] = (d > 0.0f) ? rsqrtf(d) : 0.0f; }
}

// ---------------- split fp32 -> bf16 hi/lo (vectorized x4) ----------------
__global__ void k_split4(const float* __restrict__ in,
                         __nv_bfloat16* __restrict__ hi,
                         __nv_bfloat16* __restrict__ lo, int total4) {
    int i = blockIdx.x * blockDim.x + threadIdx.x;
    if (i >= total4) return;
    float4 v = ((const float4*)in)[i];
    __nv_bfloat16 h0, l0, h1, l1, h2, l2, h3, l3;
    split2(v.x, h0, l0); split2(v.y, h1, l1);
    split2(v.z, h2, l2); split2(v.w, h3, l3);
    __nv_bfloat162* hp = (__nv_bfloat162*)hi;
    __nv_bfloat162* lp = (__nv_bfloat162*)lo;
    hp[2 * i]     = __nv_bfloat162(h0, h1);
    hp[2 * i + 1] = __nv_bfloat162(h2, h3);
    lp[2 * i]     = __nv_bfloat162(l0, l1);
    lp[2 * i + 1] = __nv_bfloat162(l2, l3);
}

// ---------------- weight transpose + split: W[K,N] -> Wt[N,K] hi/lo ----------------
__global__ void k_wsplit(const float* __restrict__ W,
                         __nv_bfloat16* __restrict__ hi,
                         __nv_bfloat16* __restrict__ lo, int K, int N) {
    int idx = blockIdx.x * blockDim.x + threadIdx.x;
    if (idx >= K * N) return;
    int n = idx / K, k = idx % K;
    __nv_bfloat16 h, l;
    split2(W[(size_t)k * N + n], h, l);
    hi[idx] = h; lo[idx] = l;
}

// ---------------- mma.sync GEMM (bf16x3 split) + fused agg-init epilogue ----------------
// D = Ahi*Bhi + Alo*Bhi + Ahi*Blo ; A[M,K] row-major, B(=Wt)[N,K] row-major.
// C = D, Cagg = bias + D * dis[row]^2.
// BM=128, BN=128, BK=32, 256 threads (8 warps: 2 M x 4 N), warp tile 64x32.
#define LDT 40                  // bf16 elements per smem row (32 data + 8 pad = 80B)
#define TILE_B (128 * LDT * 2)  // 10240 bytes per tile
#define STAGE_B (4 * TILE_B)    // Ahi,Alo,Bhi,Blo

// load one 128x32 bf16 tile into smem [128][LDT]
__device__ __forceinline__ void load_tile(uint32_t sdst, const __nv_bfloat16* __restrict__ g,
                                          int rowBase, int rowMax, int ldk, int k0, int tid) {
#pragma unroll
    for (int v = 0; v < 2; v++) {
        int idx = v * 256 + tid;          // 0..511
        int row = idx >> 2;               // 0..127
        int c   = idx & 3;                // 16B chunk
        int gr = rowBase + row; if (gr > rowMax) gr = rowMax;
        cp_async16(sdst + (uint32_t)(row * (LDT * 2) + c * 16),
                   g + (size_t)gr * ldk + k0 + c * 8);
    }
}

__global__ __launch_bounds__(256, 1)
void k_gemm3(const __nv_bfloat16* __restrict__ Ahi, const __nv_bfloat16* __restrict__ Alo,
             const __nv_bfloat16* __restrict__ Bhi, const __nv_bfloat16* __restrict__ Blo,
             float* __restrict__ C, float* __restrict__ Cagg,
             const float* __restrict__ bias, const float* __restrict__ dis,
             int M, int Ntot, int K) {
    extern __shared__ char smem[];
    const uint32_t sbase = smem_u32(smem);
    const int tid = threadIdx.x, wid = tid >> 5, lane = tid & 31;
    const int warpM = (wid & 1) * 64;     // 2 warps in M
    const int warpN = (wid >> 1) * 32;    // 4 warps in N
    const int rowBase = blockIdx.y * 128;
    const int colBase = blockIdx.x * 128;

    float acc[4][4][4];
#pragma unroll
    for (int t = 0; t < 4; t++)
#pragma unroll
        for (int u = 0; u < 4; u++)
#pragma unroll
            for (int q = 0; q < 4; q++) acc[t][u][q] = 0.0f;

    const int nk = K >> 5;   // BK=32 chunks

    // prologue: stage 0
    load_tile(sbase + 0 * TILE_B, Ahi, rowBase, M - 1, K, 0, tid);
    load_tile(sbase + 1 * TILE_B, Alo, rowBase, M - 1, K, 0, tid);
    load_tile(sbase + 2 * TILE_B, Bhi, colBase, Ntot - 1, K, 0, tid);
    load_tile(sbase + 3 * TILE_B, Blo, colBase, Ntot - 1, K, 0, tid);
    CP_COMMIT();

    const int g = lane >> 3;             // ldmatrix group 0..3
    const int l7 = lane & 7;

    for (int i = 0; i < nk; i++) {
        const uint32_t scur = sbase + (uint32_t)(i & 1) * STAGE_B;
        if (i + 1 < nk) {
            const uint32_t snxt = sbase + (uint32_t)((i + 1) & 1) * STAGE_B;
            const int k0 = (i + 1) << 5;
            load_tile(snxt + 0 * TILE_B, Ahi, rowBase, M - 1, K, k0, tid);
            load_tile(snxt + 1 * TILE_B, Alo, rowBase, M - 1, K, k0, tid);
            load_tile(snxt + 2 * TILE_B, Bhi, colBase, Ntot - 1, K, k0, tid);
            load_tile(snxt + 3 * TILE_B, Blo, colBase, Ntot - 1, K, k0, tid);
            CP_COMMIT();
            asm volatile("cp.async.wait_group 1;" ::: "memory");
        } else {
            asm volatile("cp.async.wait_group 0;" ::: "memory");
        }
        __syncthreads();

#pragma unroll
        for (int s = 0; s < 2; s++) {           // two k16 steps in BK=32
            const uint32_t kb = (uint32_t)(s * 32);
            // B fragments for all 4 n-tiles (hi & lo)
            uint32_t bh[4][2], bl[4][2];
#pragma unroll
            for (int u = 0; u < 4; u++) {
                uint32_t rB = (uint32_t)((warpN + u * 8 + l7) * (LDT * 2)) + kb + (uint32_t)((g & 1) * 16);
                ldsm_x2(scur + 2 * TILE_B + rB, bh[u][0], bh[u][1]);
                ldsm_x2(scur + 3 * TILE_B + rB, bl[u][0], bl[u][1]);
            }
#pragma unroll
            for (int t = 0; t < 4; t++) {
                uint32_t rA = (uint32_t)((warpM + t * 16 + (g & 1) * 8 + l7) * (LDT * 2))
                            + kb + (uint32_t)((g >> 1) * 16);
                uint32_t ah[4], al[4];
                ldsm_x4(scur + 0 * TILE_B + rA, ah[0], ah[1], ah[2], ah[3]);
                ldsm_x4(scur + 1 * TILE_B + rA, al[0], al[1], al[2], al[3]);
#pragma unroll
                for (int u = 0; u < 4; u++) {
                    mma_bf16(acc[t][u], ah, bh[u]);
                    mma_bf16(acc[t][u], al, bh[u]);
                    mma_bf16(acc[t][u], ah, bl[u]);
                }
            }
        }
        __syncthreads();
    }

    // ---- epilogue: C and Cagg = bias + C*dis^2 ----
#pragma unroll
    for (int t = 0; t < 4; t++) {
        const int r0 = rowBase + warpM + t * 16 + (lane >> 2);
        const int r1 = r0 + 8;
#pragma unroll
        for (int u = 0; u < 4; u++) {
            const int col = colBase + warpN + u * 8 + (lane & 3) * 2;
            float2 bv = *(const float2*)(bias + col);
            if (r0 < M) {
                float dv = dis[r0]; float d2 = dv * dv;
                size_t off = (size_t)r0 * Ntot + col;
                float2 c0 = make_float2(acc[t][u][0], acc[t][u][1]);
                *(float2*)(C + off) = c0;
                *(float2*)(Cagg + off) = make_float2(bv.x + c0.x * d2, bv.y + c0.y * d2);
            }
            if (r1 < M) {
                float dv = dis[r1]; float d2 = dv * dv;
                size_t off = (size_t)r1 * Ntot + col;
                float2 c1 = make_float2(acc[t][u][2], acc[t][u][3]);
                *(float2*)(C + off) = c1;
                *(float2*)(Cagg + off) = make_float2(bv.x + c1.x * d2, bv.y + c1.y * d2);
            }
        }
    }
}

// ---------------- edge scatter: out[dst] += t[src] * norm (warp per edge) ----------------
template <int F>
__global__ void k_edge_scatter(const int* __restrict__ ei, const float* __restrict__ ew,
                               const float* __restrict__ dis, const float* __restrict__ hin,
                               float* __restrict__ out, int e) {
    int eidx = blockIdx.x * 8 + (threadIdx.x >> 5);
    if (eidx >= e) return;
    int lane = threadIdx.x & 31;
    int s = ei[eidx];
    int d = ei[e + eidx];
    float nrm = dis[s] * ew[eidx] * dis[d];
    const float4* srcp = (const float4*)(hin + (size_t)s * F);
    float4* dstp = (float4*)(out + (size_t)d * F);
#pragma unroll
    for (int j = 0; j < F / 128; j++) {
        float4 v = srcp[lane + j * 32];
        v.x *= nrm; v.y *= nrm; v.z *= nrm; v.w *= nrm;
        red_add_v4(&dstp[lane + j * 32], v);
    }
}

// ---------------- BN(eval)+ReLU, output split to bf16 hi/lo ----------------
__global__ void k_bn_relu_split(const float* __restrict__ in,
                                const float* __restrict__ gamma, const float* __restrict__ beta,
                                const float* __restrict__ mean,  const float* __restrict__ var,
                                __nv_bfloat16* __restrict__ hi, __nv_bfloat16* __restrict__ lo,
                                int n) {
    int idx = blockIdx.x * blockDim.x + threadIdx.x;
    const int FC = HID / 4;
    if (idx >= n * FC) return;
    int c = idx % FC;
    float4 g = ((const float4*)gamma)[c];
    float4 b = ((const float4*)beta)[c];
    float4 m = ((const float4*)mean)[c];
    float4 v = ((const float4*)var)[c];
    float4 h = ((const float4*)in)[idx];
    float o0 = fmaxf((h.x - m.x) * rsqrtf(v.x + BN_EPS) * g.x + b.x, 0.0f);
    float o1 = fmaxf((h.y - m.y) * rsqrtf(v.y + BN_EPS) * g.y + b.y, 0.0f);
    float o2 = fmaxf((h.z - m.z) * rsqrtf(v.z + BN_EPS) * g.z + b.z, 0.0f);
    float o3 = fmaxf((h.w - m.w) * rsqrtf(v.w + BN_EPS) * g.w + b.w, 0.0f);
    __nv_bfloat16 h0, l0, h1, l1, h2, l2, h3, l3;
    split2(o0, h0, l0); split2(o1, h1, l1); split2(o2, h2, l2); split2(o3, h3, l3);
    __nv_bfloat162* hp = (__nv_bfloat162*)hi;
    __nv_bfloat162* lp = (__nv_bfloat162*)lo;
    hp[2 * idx]     = __nv_bfloat162(h0, h1);
    hp[2 * idx + 1] = __nv_bfloat162(h2, h3);
    lp[2 * idx]     = __nv_bfloat162(l0, l1);
    lp[2 * idx + 1] = __nv_bfloat162(l2, l3);
}

// ---------------- row L2 normalize (warp per row, F=128) ----------------
__global__ void k_l2norm(const float* __restrict__ in, float* __restrict__ out, int n) {
    int row = blockIdx.x * 8 + (threadIdx.x >> 5);
    if (row >= n) return;
    int lane = threadIdx.x & 31;
    float4 v = ((const float4*)(in + (size_t)row * OUT_DIM))[lane];
    float ss = v.x * v.x + v.y * v.y + v.z * v.z + v.w * v.w;
#pragma unroll
    for (int o = 16; o > 0; o >>= 1)
        ss += __shfl_xor_sync(0xFFFFFFFFu, ss, o);
    float inv = 1.0f / fmaxf(sqrtf(ss), NORM_EPS);
    float4 o4 = make_float4(v.x * inv, v.y * inv, v.z * inv, v.w * inv);
    ((float4*)(out + (size_t)row * OUT_DIM))[lane] = o4;
}

// ---------------- launch ----------------
extern "C" void kernel_launch(void* const* d_in, const int* in_sizes, int n_in,
                              void* d_out, int out_size) {
    const float* x   = (const float*)d_in[0];
    const int*   ei  = (const int*)d_in[1];
    const float* ew  = (const float*)d_in[2];
    const float* W1  = (const float*)d_in[3];
    const float* b1  = (const float*)d_in[4];
    const float* W2  = (const float*)d_in[5];
    const float* b2  = (const float*)d_in[6];
    const float* W3  = (const float*)d_in[7];
    const float* b3  = (const float*)d_in[8];
    const float* bn1_g = (const float*)d_in[9];
    const float* bn1_b = (const float*)d_in[10];
    const float* bn1_m = (const float*)d_in[11];
    const float* bn1_v = (const float*)d_in[12];
    const float* bn2_g = (const float*)d_in[13];
    const float* bn2_b = (const float*)d_in[14];
    const float* bn2_m = (const float*)d_in[15];
    const float* bn2_v = (const float*)d_in[16];
    float* out = (float*)d_out;

    const int n = NN;
    const int e = in_sizes[2];

    float *deg, *t, *a;
    __nv_bfloat16 *xhi, *xlo, *hhi, *hlo, *w1h, *w1l, *w2h, *w2l, *w3h, *w3l;
    cudaGetSymbolAddress((void**)&deg, g_deg);
    cudaGetSymbolAddress((void**)&t,   g_t);
    cudaGetSymbolAddress((void**)&a,   g_a);
    cudaGetSymbolAddress((void**)&xhi, g_xhi);
    cudaGetSymbolAddress((void**)&xlo, g_xlo);
    cudaGetSymbolAddress((void**)&hhi, g_hhi);
    cudaGetSymbolAddress((void**)&hlo, g_hlo);
    cudaGetSymbolAddress((void**)&w1h, g_w1hi);
    cudaGetSymbolAddress((void**)&w1l, g_w1lo);
    cudaGetSymbolAddress((void**)&w2h, g_w2hi);
    cudaGetSymbolAddress((void**)&w2l, g_w2lo);
    cudaGetSymbolAddress((void**)&w3h, g_w3hi);
    cudaGetSymbolAddress((void**)&w3l, g_w3lo);

    static bool attr_set = false;
    if (!attr_set) {
        cudaFuncSetAttribute(k_gemm3, cudaFuncAttributeMaxDynamicSharedMemorySize, 2 * STAGE_B);
        attr_set = true;
    }

    const int TB = 256;
    k_deg_init<<<(n + TB - 1) / TB, TB>>>(deg, n);
    k_deg_scatter<<<(e + TB - 1) / TB, TB>>>(ei, ew, deg, e);
    k_rsqrt<<<(n + TB - 1) / TB, TB>>>(deg, n);

    // splits
    int xt4 = n * IN_DIM / 4;
    k_split4<<<(xt4 + TB - 1) / TB, TB>>>(x, xhi, xlo, xt4);
    k_wsplit<<<(IN_DIM * HID + TB - 1) / TB, TB>>>(W1, w1h, w1l, IN_DIM, HID);
    k_wsplit<<<(HID * HID + TB - 1) / TB, TB>>>(W2, w2h, w2l, HID, HID);
    k_wsplit<<<(HID * OUT_DIM + TB - 1) / TB, TB>>>(W3, w3h, w3l, HID, OUT_DIM);

    const int mBlocks = (n + 127) / 128;      // 391
    const int eBlocks = (e + 7) / 8;
    const int nv256 = n * (HID / 4);
    const size_t smemB = 2 * STAGE_B;

    // ---- layer 1 ----
    k_gemm3<<<dim3(HID / 128, mBlocks), 256, smemB>>>(xhi, xlo, w1h, w1l,
                                                      t, a, b1, deg, n, HID, IN_DIM);
    k_edge_scatter<HID><<<eBlocks, 256>>>(ei, ew, deg, t, a, e);
    k_bn_relu_split<<<(nv256 + TB - 1) / TB, TB>>>(a, bn1_g, bn1_b, bn1_m, bn1_v, hhi, hlo, n);

    // ---- layer 2 ----
    k_gemm3<<<dim3(HID / 128, mBlocks), 256, smemB>>>(hhi, hlo, w2h, w2l,
                                                      t, a, b2, deg, n, HID, HID);
    k_edge_scatter<HID><<<eBlocks, 256>>>(ei, ew, deg, t, a, e);
    k_bn_relu_split<<<(nv256 + TB - 1) / TB, TB>>>(a, bn2_g, bn2_b, bn2_m, bn2_v, hhi, hlo, n);

    // ---- layer 3 ----
    k_gemm3<<<dim3(OUT_DIM / 128, mBlocks), 256, smemB>>>(hhi, hlo, w3h, w3l,
                                                          t, a, b3, deg, n, OUT_DIM, HID);
    k_edge_scatter<OUT_DIM><<<eBlocks, 256>>>(ei, ew, deg, t, a, e);
    k_l2norm<<<(n + 7) / 8, 256>>>(a, out, n);
}

// round 6
// speedup vs baseline: 1.1274x; 1.1274x over previous
#include <cuda_runtime.h>
#include <cuda_bf16.h>
#include <cstdint>

// ---------------- problem constants ----------------
#define NN      50000
#define EE      800000
#define IN_DIM  768
#define HID     256
#define OUT_DIM 128
#define BN_EPS  1e-5f
#define NORM_EPS 1e-12f

// ---------------- scratch (device globals — allocation-free) ----------------
__device__ float g_deg[NN];               // degree -> dis (rsqrt) in place
__device__ float g_t[(size_t)NN * HID];   // GEMM output (gather source)
__device__ float g_a[(size_t)NN * HID];   // aggregation output
__device__ float g_h[(size_t)NN * HID];   // layer input (post BN+ReLU)

// ---------------- helpers ----------------
__device__ __forceinline__ void red_add_v4(float4* p, float4 v) {
    asm volatile("red.global.add.v4.f32 [%0], {%1,%2,%3,%4};"
                 :: "l"(p), "f"(v.x), "f"(v.y), "f"(v.z), "f"(v.w)
                 : "memory");
}

__device__ __forceinline__ uint32_t smem_u32(const void* p) {
    uint32_t a;
    asm("{ .reg .u64 t; cvta.to.shared.u64 t, %1; cvt.u32.u64 %0, t; }"
        : "=r"(a) : "l"(p));
    return a;
}

__device__ __forceinline__ void cp_async16(uint32_t smem, const void* g) {
    asm volatile("cp.async.cg.shared.global [%0], [%1], 16;"
                 :: "r"(smem), "l"(g) : "memory");
}
#define CP_COMMIT() asm volatile("cp.async.commit_group;" ::: "memory")
#define CP_WAIT0()  asm volatile("cp.async.wait_group 0;" ::: "memory")

// ---- packed f32x2 (B300 dual-lane fp32 FMA; PTX-only path) ----
__device__ __forceinline__ unsigned long long pack2(float lo, float hi) {
    unsigned long long d;
    asm("mov.b64 %0, {%1, %2};" : "=l"(d) : "f"(lo), "f"(hi));
    return d;
}
__device__ __forceinline__ void unpack2(unsigned long long v, float& lo, float& hi) {
    asm("mov.b64 {%0, %1}, %2;" : "=f"(lo), "=f"(hi) : "l"(v));
}
__device__ __forceinline__ void ffma2(unsigned long long& c,
                                      unsigned long long a, unsigned long long b) {
    asm("fma.rn.f32x2 %0, %1, %2, %0;" : "+l"(c) : "l"(a), "l"(b));
}

// ---------------- degree / norm ----------------
__global__ void k_deg_init(float* deg, int n) {
    int i = blockIdx.x * blockDim.x + threadIdx.x;
    if (i < n) deg[i] = 1.0f;             // self-loop weight 1
}

__global__ void k_deg_scatter(const int* __restrict__ ei,
                              const float* __restrict__ ew,
                              float* deg, int e) {
    int i = blockIdx.x * blockDim.x + threadIdx.x;
    if (i < e) {
        int d = ei[e + i];                // dst row
        atomicAdd(&deg[d], ew[i]);
    }
}

__global__ void k_rsqrt(float* deg, int n) {
    int i = blockIdx.x * blockDim.x + threadIdx.x;
    if (i < n) {
        float d = deg[i];
        deg[i] = (d > 0.0f) ? rsqrtf(d) : 0.0f;
    }
}

// ---------------- SGEMM (FFMA2) fused with agg-init epilogue ----------------
// C[M,N] = A[M,K] @ B[K,N];  Cagg = bias + C * dis[row]^2
// BM=128, BN=128, BK=16, 256 threads, 8x8/thread (as 8x4 f32x2 lanes),
// 2-stage pipeline: B via cp.async, A register-staged (transposed into smem).
__global__ __launch_bounds__(256, 2)
void k_sgemm_fused(const float* __restrict__ A, const float* __restrict__ B,
                   float* __restrict__ C, float* __restrict__ Cagg,
                   const float* __restrict__ bias, const float* __restrict__ dis,
                   int M, int N, int K) {
    __shared__ float As[2][16][128];
    __shared__ float Bs[2][16][128];

    const int tid = threadIdx.x;
    const int tx  = tid & 15;        // 0..15
    const int ty  = tid >> 4;        // 0..15
    const int blockRow = blockIdx.y;
    const int blockCol = blockIdx.x;

    const int aRow = tid >> 2;           // 0..63
    const int aCol = (tid & 3) * 4;      // 0,4,8,12
    const int bRow = tid >> 5;           // 0..7
    const int bCol = (tid & 31) * 4;     // 0..124

    const float* Ablk = A + (size_t)blockRow * 128 * K;
    const float* Bblk = B + blockCol * 128;

    unsigned long long acc2[8][4];
#pragma unroll
    for (int i = 0; i < 8; i++)
#pragma unroll
        for (int j = 0; j < 4; j++) acc2[i][j] = 0ull;

    float4 ra[2];

    // ---- prologue: stage tile k0=0 into buffer 0 ----
#pragma unroll
    for (int r = 0; r < 2; r++) {
        int row  = aRow + r * 64;
        int grow = blockRow * 128 + row;
        ra[r] = make_float4(0.f, 0.f, 0.f, 0.f);
        if (grow < M)
            ra[r] = *(const float4*)(Ablk + (size_t)row * K + aCol);
    }
#pragma unroll
    for (int r = 0; r < 2; r++) {
        int row = bRow + r * 8;
        cp_async16(smem_u32(&Bs[0][row][bCol]),
                   Bblk + (size_t)row * N + bCol);
    }
    CP_COMMIT();
#pragma unroll
    for (int r = 0; r < 2; r++) {
        int row = aRow + r * 64;
        As[0][aCol + 0][row] = ra[r].x;
        As[0][aCol + 1][row] = ra[r].y;
        As[0][aCol + 2][row] = ra[r].z;
        As[0][aCol + 3][row] = ra[r].w;
    }
    CP_WAIT0();
    __syncthreads();

    int buf = 0;
    for (int k0 = 16; k0 < K; k0 += 16) {
        int nbuf = buf ^ 1;
#pragma unroll
        for (int r = 0; r < 2; r++) {
            int row = bRow + r * 8;
            cp_async16(smem_u32(&Bs[nbuf][row][bCol]),
                       Bblk + (size_t)(k0 + row) * N + bCol);
        }
        CP_COMMIT();
#pragma unroll
        for (int r = 0; r < 2; r++) {
            int row  = aRow + r * 64;
            int grow = blockRow * 128 + row;
            ra[r] = make_float4(0.f, 0.f, 0.f, 0.f);
            if (grow < M)
                ra[r] = *(const float4*)(Ablk + (size_t)row * K + k0 + aCol);
        }

        // compute current tile (FFMA2)
#pragma unroll
        for (int kk = 0; kk < 16; kk++) {
            float4 a0 = *(const float4*)&As[buf][kk][ty * 8];
            float4 a1 = *(const float4*)&As[buf][kk][ty * 8 + 4];
            ulonglong2 bb0 = *(const ulonglong2*)&Bs[buf][kk][tx * 8];
            ulonglong2 bb1 = *(const ulonglong2*)&Bs[buf][kk][tx * 8 + 4];
            unsigned long long b2[4] = {bb0.x, bb0.y, bb1.x, bb1.y};
            unsigned long long a2[8] = {
                pack2(a0.x, a0.x), pack2(a0.y, a0.y), pack2(a0.z, a0.z), pack2(a0.w, a0.w),
                pack2(a1.x, a1.x), pack2(a1.y, a1.y), pack2(a1.z, a1.z), pack2(a1.w, a1.w)};
#pragma unroll
            for (int i = 0; i < 8; i++)
#pragma unroll
                for (int j = 0; j < 4; j++)
                    ffma2(acc2[i][j], a2[i], b2[j]);
        }

#pragma unroll
        for (int r = 0; r < 2; r++) {
            int row = aRow + r * 64;
            As[nbuf][aCol + 0][row] = ra[r].x;
            As[nbuf][aCol + 1][row] = ra[r].y;
            As[nbuf][aCol + 2][row] = ra[r].z;
            As[nbuf][aCol + 3][row] = ra[r].w;
        }
        CP_WAIT0();
        __syncthreads();
        buf = nbuf;
    }

    // final tile
#pragma unroll
    for (int kk = 0; kk < 16; kk++) {
        float4 a0 = *(const float4*)&As[buf][kk][ty * 8];
        float4 a1 = *(const float4*)&As[buf][kk][ty * 8 + 4];
        ulonglong2 bb0 = *(const ulonglong2*)&Bs[buf][kk][tx * 8];
        ulonglong2 bb1 = *(const ulonglong2*)&Bs[buf][kk][tx * 8 + 4];
        unsigned long long b2[4] = {bb0.x, bb0.y, bb1.x, bb1.y};
        unsigned long long a2[8] = {
            pack2(a0.x, a0.x), pack2(a0.y, a0.y), pack2(a0.z, a0.z), pack2(a0.w, a0.w),
            pack2(a1.x, a1.x), pack2(a1.y, a1.y), pack2(a1.z, a1.z), pack2(a1.w, a1.w)};
#pragma unroll
        for (int i = 0; i < 8; i++)
#pragma unroll
            for (int j = 0; j < 4; j++)
                ffma2(acc2[i][j], a2[i], b2[j]);
    }

    // ---- epilogue: write C and Cagg = bias + C*dis^2 ----
    int colBase = blockCol * 128 + tx * 8;
    float4 bv0 = *(const float4*)(bias + colBase);
    float4 bv1 = *(const float4*)(bias + colBase + 4);
#pragma unroll
    for (int i = 0; i < 8; i++) {
        int grow = blockRow * 128 + ty * 8 + i;
        if (grow >= M) continue;
        float dv = dis[grow];
        float d2 = dv * dv;
        size_t off = (size_t)grow * N + colBase;
        float4 c0, c1;
        unpack2(acc2[i][0], c0.x, c0.y);
        unpack2(acc2[i][1], c0.z, c0.w);
        unpack2(acc2[i][2], c1.x, c1.y);
        unpack2(acc2[i][3], c1.z, c1.w);
        *(float4*)(C + off)     = c0;
        *(float4*)(C + off + 4) = c1;
        float4 g0, g1;
        g0.x = bv0.x + c0.x * d2; g0.y = bv0.y + c0.y * d2;
        g0.z = bv0.z + c0.z * d2; g0.w = bv0.w + c0.w * d2;
        g1.x = bv1.x + c1.x * d2; g1.y = bv1.y + c1.y * d2;
        g1.z = bv1.z + c1.z * d2; g1.w = bv1.w + c1.w * d2;
        *(float4*)(Cagg + off)     = g0;
        *(float4*)(Cagg + off + 4) = g1;
    }
}

// ---------------- edge scatter: out[dst] += t[src] * norm (warp per edge) ----------------
template <int F>
__global__ void k_edge_scatter(const int* __restrict__ ei,
                               const float* __restrict__ ew,
                               const float* __restrict__ dis,
                               const float* __restrict__ hin,
                               float* __restrict__ out, int e) {
    int eidx = blockIdx.x * 8 + (threadIdx.x >> 5);
    if (eidx >= e) return;
    int lane = threadIdx.x & 31;
    int s = ei[eidx];
    int d = ei[e + eidx];
    float nrm = dis[s] * ew[eidx] * dis[d];
    const float4* srcp = (const float4*)(hin + (size_t)s * F);
    float4* dstp = (float4*)(out + (size_t)d * F);
#pragma unroll
    for (int j = 0; j < F / 128; j++) {
        float4 v = srcp[lane + j * 32];
        v.x *= nrm; v.y *= nrm; v.z *= nrm; v.w *= nrm;
        red_add_v4(&dstp[lane + j * 32], v);
    }
}

// ---------------- BN (eval) + ReLU ----------------
template <int F>
__global__ void k_bn_relu(const float* __restrict__ in,
                          const float* __restrict__ gamma,
                          const float* __restrict__ beta,
                          const float* __restrict__ mean,
                          const float* __restrict__ var,
                          float* __restrict__ out, int n) {
    int idx = blockIdx.x * blockDim.x + threadIdx.x;
    const int FC = F / 4;
    if (idx >= n * FC) return;
    int c = idx % FC;
    float4 g = ((const float4*)gamma)[c];
    float4 b = ((const float4*)beta)[c];
    float4 m = ((const float4*)mean)[c];
    float4 v = ((const float4*)var)[c];
    float4 h = ((const float4*)in)[idx];
    float4 o;
    o.x = fmaxf((h.x - m.x) * rsqrtf(v.x + BN_EPS) * g.x + b.x, 0.0f);
    o.y = fmaxf((h.y - m.y) * rsqrtf(v.y + BN_EPS) * g.y + b.y, 0.0f);
    o.z = fmaxf((h.z - m.z) * rsqrtf(v.z + BN_EPS) * g.z + b.z, 0.0f);
    o.w = fmaxf((h.w - m.w) * rsqrtf(v.w + BN_EPS) * g.w + b.w, 0.0f);
    ((float4*)out)[idx] = o;
}

// ---------------- row L2 normalize (warp per row, F=128) ----------------
__global__ void k_l2norm(const float* __restrict__ in, float* __restrict__ out, int n) {
    int row = blockIdx.x * 8 + (threadIdx.x >> 5);
    if (row >= n) return;
    int lane = threadIdx.x & 31;
    float4 v = ((const float4*)(in + (size_t)row * OUT_DIM))[lane];
    float ss = v.x * v.x + v.y * v.y + v.z * v.z + v.w * v.w;
#pragma unroll
    for (int o = 16; o > 0; o >>= 1)
        ss += __shfl_xor_sync(0xFFFFFFFFu, ss, o);
    float inv = 1.0f / fmaxf(sqrtf(ss), NORM_EPS);
    float4 o4 = make_float4(v.x * inv, v.y * inv, v.z * inv, v.w * inv);
    ((float4*)(out + (size_t)row * OUT_DIM))[lane] = o4;
}

// ---------------- launch ----------------
extern "C" void kernel_launch(void* const* d_in, const int* in_sizes, int n_in,
                              void* d_out, int out_size) {
    const float* x   = (const float*)d_in[0];
    const int*   ei  = (const int*)d_in[1];     // int32 (JAX x64 disabled)
    const float* ew  = (const float*)d_in[2];
    const float* W1  = (const float*)d_in[3];
    const float* b1  = (const float*)d_in[4];
    const float* W2  = (const float*)d_in[5];
    const float* b2  = (const float*)d_in[6];
    const float* W3  = (const float*)d_in[7];
    const float* b3  = (const float*)d_in[8];
    const float* bn1_g = (const float*)d_in[9];
    const float* bn1_b = (const float*)d_in[10];
    const float* bn1_m = (const float*)d_in[11];
    const float* bn1_v = (const float*)d_in[12];
    const float* bn2_g = (const float*)d_in[13];
    const float* bn2_b = (const float*)d_in[14];
    const float* bn2_m = (const float*)d_in[15];
    const float* bn2_v = (const float*)d_in[16];
    float* out = (float*)d_out;

    const int n = NN;
    const int e = in_sizes[2];   // 800000

    float *deg, *t, *a, *h;
    cudaGetSymbolAddress((void**)&deg, g_deg);
    cudaGetSymbolAddress((void**)&t,   g_t);
    cudaGetSymbolAddress((void**)&a,   g_a);
    cudaGetSymbolAddress((void**)&h,   g_h);

    const int TB = 256;
    // degree -> dis
    k_deg_init<<<(n + TB - 1) / TB, TB>>>(deg, n);
    k_deg_scatter<<<(e + TB - 1) / TB, TB>>>(ei, ew, deg, e);
    k_rsqrt<<<(n + TB - 1) / TB, TB>>>(deg, n);

    dim3 gemm_block(256);
    int mBlocks = (n + 127) / 128;
    int eBlocks = (e + 7) / 8;
    int nv256 = n * (HID / 4);

    // ---- layer 1: x@W1 (+agg init) -> scatter -> bn1+relu ----
    {
        dim3 grid(HID / 128, mBlocks);
        k_sgemm_fused<<<grid, gemm_block>>>(x, W1, t, a, b1, deg, n, HID, IN_DIM);
    }
    k_edge_scatter<HID><<<eBlocks, 256>>>(ei, ew, deg, t, a, e);
    k_bn_relu<HID><<<(nv256 + TB - 1) / TB, TB>>>(a, bn1_g, bn1_b, bn1_m, bn1_v, h, n);

    // ---- layer 2 ----
    {
        dim3 grid(HID / 128, mBlocks);
        k_sgemm_fused<<<grid, gemm_block>>>(h, W2, t, a, b2, deg, n, HID, HID);
    }
    k_edge_scatter<HID><<<eBlocks, 256>>>(ei, ew, deg, t, a, e);
    k_bn_relu<HID><<<(nv256 + TB - 1) / TB, TB>>>(a, bn2_g, bn2_b, bn2_m, bn2_v, h, n);

    // ---- layer 3 ----
    {
        dim3 grid(OUT_DIM / 128, mBlocks);
        k_sgemm_fused<<<grid, gemm_block>>>(h, W3, t, a, b3, deg, n, OUT_DIM, HID);
    }
    k_edge_scatter<OUT_DIM><<<eBlocks, 256>>>(ei, ew, deg, t, a, e);
    k_l2norm<<<(n + 7) / 8, 256>>>(a, out, n);
}

// round 7
// speedup vs baseline: 1.3549x; 1.2018x over previous
#include <cuda_runtime.h>
#include <cuda_bf16.h>
#include <cstdint>

// ---------------- problem constants ----------------
#define NN      50000
#define EE      800000
#define IN_DIM  768
#define HID     256
#define OUT_DIM 128
#define BN_EPS  1e-5f
#define NORM_EPS 1e-12f

// ---------------- scratch (device globals — allocation-free) ----------------
__device__ float g_deg[NN];               // weighted degree -> dis (rsqrt) in place
__device__ float g_t[(size_t)NN * HID];   // GEMM output (gather source)
__device__ float g_h[(size_t)NN * HID];   // layer input (post BN+ReLU)
__device__ int   g_cnt[NN];               // in-degree count
__device__ int   g_off[NN + 1];           // CSR offsets
__device__ int   g_cursor[NN];            // placement cursors
__device__ int   g_csr_src[EE];           // src node per CSR slot
__device__ float g_csr_nrm[EE];           // edge norm per CSR slot

// ---------------- helpers ----------------
__device__ __forceinline__ uint32_t smem_u32(const void* p) {
    uint32_t a;
    asm("{ .reg .u64 t; cvta.to.shared.u64 t, %1; cvt.u32.u64 %0, t; }"
        : "=r"(a) : "l"(p));
    return a;
}

__device__ __forceinline__ void cp_async16(uint32_t smem, const void* g) {
    asm volatile("cp.async.cg.shared.global [%0], [%1], 16;"
                 :: "r"(smem), "l"(g) : "memory");
}
#define CP_COMMIT() asm volatile("cp.async.commit_group;" ::: "memory")
#define CP_WAIT0()  asm volatile("cp.async.wait_group 0;" ::: "memory")

// ---- packed f32x2 ----
__device__ __forceinline__ unsigned long long pack2(float lo, float hi) {
    unsigned long long d;
    asm("mov.b64 %0, {%1, %2};" : "=l"(d) : "f"(lo), "f"(hi));
    return d;
}
__device__ __forceinline__ void unpack2(unsigned long long v, float& lo, float& hi) {
    asm("mov.b64 {%0, %1}, %2;" : "=f"(lo), "=f"(hi) : "l"(v));
}
__device__ __forceinline__ void ffma2(unsigned long long& c,
                                      unsigned long long a, unsigned long long b) {
    asm("fma.rn.f32x2 %0, %1, %2, %0;" : "+l"(c) : "l"(a), "l"(b));
}

// ---------------- degree / count ----------------
__global__ void k_init(float* deg, int* cnt, int n) {
    int i = blockIdx.x * blockDim.x + threadIdx.x;
    if (i < n) { deg[i] = 1.0f; cnt[i] = 0; }   // self-loop weight 1
}

__global__ void k_deg_cnt(const int* __restrict__ ei, const float* __restrict__ ew,
                          float* deg, int* cnt, int e) {
    int i = blockIdx.x * blockDim.x + threadIdx.x;
    if (i < e) {
        int d = ei[e + i];
        atomicAdd(&deg[d], ew[i]);
        atomicAdd(&cnt[d], 1);
    }
}

__global__ void k_rsqrt(float* deg, int n) {
    int i = blockIdx.x * blockDim.x + threadIdx.x;
    if (i < n) { float d = deg[i]; deg[i] = (d > 0.0f) ? rsqrtf(d) : 0.0f; }
}

// ---------------- single-block exclusive scan over cnt -> off, cursor ----------------
__global__ void k_scan(const int* __restrict__ cnt, int* __restrict__ off,
                       int* __restrict__ cursor, int n) {
    __shared__ int sums[1024];
    const int t = threadIdx.x;
    const int per = (n + 1023) / 1024;
    const int start = t * per;
    const int end = min(start + per, n);
    int s = 0;
    for (int i = start; i < end; i++) s += cnt[i];
    sums[t] = s;
    __syncthreads();
    for (int d = 1; d < 1024; d <<= 1) {
        int v = (t >= d) ? sums[t - d] : 0;
        __syncthreads();
        sums[t] += v;
        __syncthreads();
    }
    int run = (t == 0) ? 0 : sums[t - 1];
    for (int i = start; i < end; i++) {
        off[i] = run; cursor[i] = run; run += cnt[i];
    }
    if (t == 1023) off[n] = run;
}

// ---------------- CSR placement + norm precompute ----------------
__global__ void k_place(const int* __restrict__ ei, const float* __restrict__ ew,
                        const float* __restrict__ dis,
                        int* __restrict__ cursor,
                        int* __restrict__ csrc, float* __restrict__ cnrm, int e) {
    int i = blockIdx.x * blockDim.x + threadIdx.x;
    if (i >= e) return;
    int s = ei[i];
    int d = ei[e + i];
    float nrm = dis[s] * ew[i] * dis[d];
    int pos = atomicAdd(&cursor[d], 1);
    csrc[pos] = s;
    cnrm[pos] = nrm;
}

// ---------------- SGEMM (FFMA2), plain C epilogue ----------------
// BM=128, BN=128, BK=16, 256 threads, 8x8/thread, 2-stage pipeline.
__global__ __launch_bounds__(256, 2)
void k_sgemm(const float* __restrict__ A, const float* __restrict__ B,
             float* __restrict__ C, int M, int N, int K) {
    __shared__ float As[2][16][128];
    __shared__ float Bs[2][16][128];

    const int tid = threadIdx.x;
    const int tx  = tid & 15;
    const int ty  = tid >> 4;
    const int blockRow = blockIdx.y;
    const int blockCol = blockIdx.x;

    const int aRow = tid >> 2;
    const int aCol = (tid & 3) * 4;
    const int bRow = tid >> 5;
    const int bCol = (tid & 31) * 4;

    const float* Ablk = A + (size_t)blockRow * 128 * K;
    const float* Bblk = B + blockCol * 128;

    unsigned long long acc2[8][4];
#pragma unroll
    for (int i = 0; i < 8; i++)
#pragma unroll
        for (int j = 0; j < 4; j++) acc2[i][j] = 0ull;

    float4 ra[2];

#pragma unroll
    for (int r = 0; r < 2; r++) {
        int row  = aRow + r * 64;
        int grow = blockRow * 128 + row;
        ra[r] = make_float4(0.f, 0.f, 0.f, 0.f);
        if (grow < M)
            ra[r] = *(const float4*)(Ablk + (size_t)row * K + aCol);
    }
#pragma unroll
    for (int r = 0; r < 2; r++) {
        int row = bRow + r * 8;
        cp_async16(smem_u32(&Bs[0][row][bCol]), Bblk + (size_t)row * N + bCol);
    }
    CP_COMMIT();
#pragma unroll
    for (int r = 0; r < 2; r++) {
        int row = aRow + r * 64;
        As[0][aCol + 0][row] = ra[r].x;
        As[0][aCol + 1][row] = ra[r].y;
        As[0][aCol + 2][row] = ra[r].z;
        As[0][aCol + 3][row] = ra[r].w;
    }
    CP_WAIT0();
    __syncthreads();

    int buf = 0;
    for (int k0 = 16; k0 < K; k0 += 16) {
        int nbuf = buf ^ 1;
#pragma unroll
        for (int r = 0; r < 2; r++) {
            int row = bRow + r * 8;
            cp_async16(smem_u32(&Bs[nbuf][row][bCol]),
                       Bblk + (size_t)(k0 + row) * N + bCol);
        }
        CP_COMMIT();
#pragma unroll
        for (int r = 0; r < 2; r++) {
            int row  = aRow + r * 64;
            int grow = blockRow * 128 + row;
            ra[r] = make_float4(0.f, 0.f, 0.f, 0.f);
            if (grow < M)
                ra[r] = *(const float4*)(Ablk + (size_t)row * K + k0 + aCol);
        }

#pragma unroll
        for (int kk = 0; kk < 16; kk++) {
            float4 a0 = *(const float4*)&As[buf][kk][ty * 8];
            float4 a1 = *(const float4*)&As[buf][kk][ty * 8 + 4];
            ulonglong2 bb0 = *(const ulonglong2*)&Bs[buf][kk][tx * 8];
            ulonglong2 bb1 = *(const ulonglong2*)&Bs[buf][kk][tx * 8 + 4];
            unsigned long long b2[4] = {bb0.x, bb0.y, bb1.x, bb1.y};
            unsigned long long a2[8] = {
                pack2(a0.x, a0.x), pack2(a0.y, a0.y), pack2(a0.z, a0.z), pack2(a0.w, a0.w),
                pack2(a1.x, a1.x), pack2(a1.y, a1.y), pack2(a1.z, a1.z), pack2(a1.w, a1.w)};
#pragma unroll
            for (int i = 0; i < 8; i++)
#pragma unroll
                for (int j = 0; j < 4; j++)
                    ffma2(acc2[i][j], a2[i], b2[j]);
        }

#pragma unroll
        for (int r = 0; r < 2; r++) {
            int row = aRow + r * 64;
            As[nbuf][aCol + 0][row] = ra[r].x;
            As[nbuf][aCol + 1][row] = ra[r].y;
            As[nbuf][aCol + 2][row] = ra[r].z;
            As[nbuf][aCol + 3][row] = ra[r].w;
        }
        CP_WAIT0();
        __syncthreads();
        buf = nbuf;
    }

#pragma unroll
    for (int kk = 0; kk < 16; kk++) {
        float4 a0 = *(const float4*)&As[buf][kk][ty * 8];
        float4 a1 = *(const float4*)&As[buf][kk][ty * 8 + 4];
        ulonglong2 bb0 = *(const ulonglong2*)&Bs[buf][kk][tx * 8];
        ulonglong2 bb1 = *(const ulonglong2*)&Bs[buf][kk][tx * 8 + 4];
        unsigned long long b2[4] = {bb0.x, bb0.y, bb1.x, bb1.y};
        unsigned long long a2[8] = {
            pack2(a0.x, a0.x), pack2(a0.y, a0.y), pack2(a0.z, a0.z), pack2(a0.w, a0.w),
            pack2(a1.x, a1.x), pack2(a1.y, a1.y), pack2(a1.z, a1.z), pack2(a1.w, a1.w)};
#pragma unroll
        for (int i = 0; i < 8; i++)
#pragma unroll
            for (int j = 0; j < 4; j++)
                ffma2(acc2[i][j], a2[i], b2[j]);
    }

    int colBase = blockCol * 128 + tx * 8;
#pragma unroll
    for (int i = 0; i < 8; i++) {
        int grow = blockRow * 128 + ty * 8 + i;
        if (grow >= M) continue;
        size_t off = (size_t)grow * N + colBase;
        float4 c0, c1;
        unpack2(acc2[i][0], c0.x, c0.y);
        unpack2(acc2[i][1], c0.z, c0.w);
        unpack2(acc2[i][2], c1.x, c1.y);
        unpack2(acc2[i][3], c1.z, c1.w);
        *(float4*)(C + off)     = c0;
        *(float4*)(C + off + 4) = c1;
    }
}

// ---------------- fused CSR aggregation + BN/ReLU or L2norm ----------------
// out[row] = POST( bias + dis[row]^2 * t[row] + sum_e nrm[e] * t[src[e]] )
// warp per row; lane holds F/128 float4 accumulators.
template <int F, bool FINAL>
__global__ __launch_bounds__(256)
void k_agg(const float* __restrict__ t,
           const int* __restrict__ off, const int* __restrict__ csrc,
           const float* __restrict__ cnrm,
           const float* __restrict__ bias, const float* __restrict__ dis,
           const float* __restrict__ bg, const float* __restrict__ bb,
           const float* __restrict__ bm, const float* __restrict__ bv,
           float* __restrict__ out, int n) {
    const int row = blockIdx.x * 8 + (threadIdx.x >> 5);
    if (row >= n) return;
    const int lane = threadIdx.x & 31;
    constexpr int V = F / 128;

    float4 acc[V];
    {
        const float dvv = dis[row];
        const float d2 = dvv * dvv;
        const float4* trow = (const float4*)(t + (size_t)row * F);
#pragma unroll
        for (int j = 0; j < V; j++) {
            float4 tv = trow[lane + j * 32];
            float4 bvv = ((const float4*)bias)[lane + j * 32];
            acc[j].x = bvv.x + tv.x * d2;
            acc[j].y = bvv.y + tv.y * d2;
            acc[j].z = bvv.z + tv.z * d2;
            acc[j].w = bvv.w + tv.w * d2;
        }
    }

    int e = __ldg(&off[row]);
    const int e1 = __ldg(&off[row + 1]);
    for (; e + 1 < e1; e += 2) {
        int s0 = __ldg(&csrc[e]);
        int s1 = __ldg(&csrc[e + 1]);
        float w0 = __ldg(&cnrm[e]);
        float w1 = __ldg(&cnrm[e + 1]);
        const float4* r0 = (const float4*)(t + (size_t)s0 * F);
        const float4* r1 = (const float4*)(t + (size_t)s1 * F);
#pragma unroll
        for (int j = 0; j < V; j++) {
            float4 x0 = r0[lane + j * 32];
            float4 x1 = r1[lane + j * 32];
            acc[j].x += w0 * x0.x + w1 * x1.x;
            acc[j].y += w0 * x0.y + w1 * x1.y;
            acc[j].z += w0 * x0.z + w1 * x1.z;
            acc[j].w += w0 * x0.w + w1 * x1.w;
        }
    }
    if (e < e1) {
        int s0 = __ldg(&csrc[e]);
        float w0 = __ldg(&cnrm[e]);
        const float4* r0 = (const float4*)(t + (size_t)s0 * F);
#pragma unroll
        for (int j = 0; j < V; j++) {
            float4 x0 = r0[lane + j * 32];
            acc[j].x += w0 * x0.x;
            acc[j].y += w0 * x0.y;
            acc[j].z += w0 * x0.z;
            acc[j].w += w0 * x0.w;
        }
    }

    if (FINAL) {
        // L2 normalize (F = 128, V = 1)
        float ss = acc[0].x * acc[0].x + acc[0].y * acc[0].y
                 + acc[0].z * acc[0].z + acc[0].w * acc[0].w;
#pragma unroll
        for (int o = 16; o > 0; o >>= 1)
            ss += __shfl_xor_sync(0xFFFFFFFFu, ss, o);
        float inv = 1.0f / fmaxf(sqrtf(ss), NORM_EPS);
        float4 o4 = make_float4(acc[0].x * inv, acc[0].y * inv,
                                acc[0].z * inv, acc[0].w * inv);
        ((float4*)(out + (size_t)row * F))[lane] = o4;
    } else {
        float4* orow = (float4*)(out + (size_t)row * F);
#pragma unroll
        for (int j = 0; j < V; j++) {
            int c = lane + j * 32;
            float4 g = ((const float4*)bg)[c];
            float4 b = ((const float4*)bb)[c];
            float4 m = ((const float4*)bm)[c];
            float4 v = ((const float4*)bv)[c];
            float4 o;
            o.x = fmaxf((acc[j].x - m.x) * rsqrtf(v.x + BN_EPS) * g.x + b.x, 0.0f);
            o.y = fmaxf((acc[j].y - m.y) * rsqrtf(v.y + BN_EPS) * g.y + b.y, 0.0f);
            o.z = fmaxf((acc[j].z - m.z) * rsqrtf(v.z + BN_EPS) * g.z + b.z, 0.0f);
            o.w = fmaxf((acc[j].w - m.w) * rsqrtf(v.w + BN_EPS) * g.w + b.w, 0.0f);
            orow[c] = o;
        }
    }
}

// ---------------- launch ----------------
extern "C" void kernel_launch(void* const* d_in, const int* in_sizes, int n_in,
                              void* d_out, int out_size) {
    const float* x   = (const float*)d_in[0];
    const int*   ei  = (const int*)d_in[1];     // int32 (JAX x64 disabled)
    const float* ew  = (const float*)d_in[2];
    const float* W1  = (const float*)d_in[3];
    const float* b1  = (const float*)d_in[4];
    const float* W2  = (const float*)d_in[5];
    const float* b2  = (const float*)d_in[6];
    const float* W3  = (const float*)d_in[7];
    const float* b3  = (const float*)d_in[8];
    const float* bn1_g = (const float*)d_in[9];
    const float* bn1_b = (const float*)d_in[10];
    const float* bn1_m = (const float*)d_in[11];
    const float* bn1_v = (const float*)d_in[12];
    const float* bn2_g = (const float*)d_in[13];
    const float* bn2_b = (const float*)d_in[14];
    const float* bn2_m = (const float*)d_in[15];
    const float* bn2_v = (const float*)d_in[16];
    float* out = (float*)d_out;

    const int n = NN;
    const int e = in_sizes[2];   // 800000

    float *deg, *t, *h, *cnrm;
    int *cnt, *off, *cursor, *csrc;
    cudaGetSymbolAddress((void**)&deg, g_deg);
    cudaGetSymbolAddress((void**)&t,   g_t);
    cudaGetSymbolAddress((void**)&h,   g_h);
    cudaGetSymbolAddress((void**)&cnt, g_cnt);
    cudaGetSymbolAddress((void**)&off, g_off);
    cudaGetSymbolAddress((void**)&cursor, g_cursor);
    cudaGetSymbolAddress((void**)&csrc, g_csr_src);
    cudaGetSymbolAddress((void**)&cnrm, g_csr_nrm);

    const int TB = 256;
    // ---- graph preprocessing ----
    k_init<<<(n + TB - 1) / TB, TB>>>(deg, cnt, n);
    k_deg_cnt<<<(e + TB - 1) / TB, TB>>>(ei, ew, deg, cnt, e);
    k_rsqrt<<<(n + TB - 1) / TB, TB>>>(deg, n);
    k_scan<<<1, 1024>>>(cnt, off, cursor, n);
    k_place<<<(e + TB - 1) / TB, TB>>>(ei, ew, deg, cursor, csrc, cnrm, e);

    const int mBlocks = (n + 127) / 128;
    const int aBlocks = (n + 7) / 8;

    // ---- layer 1 ----
    k_sgemm<<<dim3(HID / 128, mBlocks), 256>>>(x, W1, t, n, HID, IN_DIM);
    k_agg<HID, false><<<aBlocks, 256>>>(t, off, csrc, cnrm, b1, deg,
                                        bn1_g, bn1_b, bn1_m, bn1_v, h, n);
    // ---- layer 2 ----
    k_sgemm<<<dim3(HID / 128, mBlocks), 256>>>(h, W2, t, n, HID, HID);
    k_agg<HID, false><<<aBlocks, 256>>>(t, off, csrc, cnrm, b2, deg,
                                        bn2_g, bn2_b, bn2_m, bn2_v, h, n);
    // ---- layer 3 ----
    k_sgemm<<<dim3(OUT_DIM / 128, mBlocks), 256>>>(h, W3, t, n, OUT_DIM, HID);
    k_agg<OUT_DIM, true><<<aBlocks, 256>>>(t, off, csrc, cnrm, b3, deg,
                                           nullptr, nullptr, nullptr, nullptr, out, n);
}

// round 9
// speedup vs baseline: 1.4632x; 1.0799x over previous
#include <cuda_runtime.h>
#include <cuda_bf16.h>
#include <cstdint>

// ---------------- problem constants ----------------
#define NN      50000
#define EE      800000
#define IN_DIM  768
#define HID     256
#define OUT_DIM 128
#define BN_EPS  1e-5f
#define NORM_EPS 1e-12f
#define NBLK    ((NN + 255) / 256)

// ---------------- scratch (device globals — allocation-free) ----------------
__device__ float g_deg[NN];               // weighted degree -> dis (rsqrt) in place
__device__ float g_t[(size_t)NN * HID];   // GEMM output (gather source)
__device__ float g_h[(size_t)NN * HID];   // layer input (post BN+ReLU)
__device__ int   g_cnt[NN];               // in-degree count
__device__ int   g_off[NN + 1];           // CSR offsets
__device__ int   g_cursor[NN];            // placement cursors
__device__ int   g_part[NBLK];            // per-block partial sums
__device__ int   g_csr_src[EE];           // src node per CSR slot
__device__ float g_csr_nrm[EE];           // edge norm per CSR slot

// ---------------- helpers ----------------
__device__ __forceinline__ uint32_t smem_u32(const void* p) {
    uint32_t a;
    asm("{ .reg .u64 t; cvta.to.shared.u64 t, %1; cvt.u32.u64 %0, t; }"
        : "=r"(a) : "l"(p));
    return a;
}

__device__ __forceinline__ void cp_async16(uint32_t smem, const void* g) {
    asm volatile("cp.async.cg.shared.global [%0], [%1], 16;"
                 :: "r"(smem), "l"(g) : "memory");
}
#define CP_COMMIT() asm volatile("cp.async.commit_group;" ::: "memory")
#define CP_WAIT0()  asm volatile("cp.async.wait_group 0;" ::: "memory")

// ---- packed f32x2 ----
__device__ __forceinline__ unsigned long long pack2(float v) {
    unsigned long long d;
    asm("mov.b64 %0, {%1, %1};" : "=l"(d) : "f"(v));
    return d;
}
__device__ __forceinline__ void unpack2(unsigned long long v, float& lo, float& hi) {
    asm("mov.b64 {%0, %1}, %2;" : "=f"(lo), "=f"(hi) : "l"(v));
}
__device__ __forceinline__ void ffma2(unsigned long long& c,
                                      unsigned long long a, unsigned long long b) {
    asm("fma.rn.f32x2 %0, %1, %2, %0;" : "+l"(c) : "l"(a), "l"(b));
}

// ---------------- degree / count ----------------
__global__ void k_init(float* deg, int* cnt, int n) {
    int i = blockIdx.x * blockDim.x + threadIdx.x;
    if (i < n) { deg[i] = 1.0f; cnt[i] = 0; }   // self-loop weight 1
}

__global__ void k_deg_cnt(const int* __restrict__ ei, const float* __restrict__ ew,
                          float* deg, int* cnt, int e) {
    int i = blockIdx.x * blockDim.x + threadIdx.x;
    if (i < e) {
        int d = ei[e + i];
        atomicAdd(&deg[d], ew[i]);
        atomicAdd(&cnt[d], 1);
    }
}

__global__ void k_rsqrt(float* deg, int n) {
    int i = blockIdx.x * blockDim.x + threadIdx.x;
    if (i < n) { float d = deg[i]; deg[i] = (d > 0.0f) ? rsqrtf(d) : 0.0f; }
}

// ---------------- multi-block exclusive scan: cnt -> off, cursor ----------------
__device__ __forceinline__ int warp_incl_scan(int v, int lane) {
#pragma unroll
    for (int o = 1; o < 32; o <<= 1) {
        int t = __shfl_up_sync(0xFFFFFFFFu, v, o);
        if (lane >= o) v += t;
    }
    return v;
}

__device__ __forceinline__ int block_incl_scan(int v, int tid) {
    __shared__ int ws[8];
    const int lane = tid & 31, w = tid >> 5;
    int s = warp_incl_scan(v, lane);
    if (lane == 31) ws[w] = s;
    __syncthreads();
    if (w == 0) {
        int t = (lane < 8) ? ws[lane] : 0;
        t = warp_incl_scan(t, lane);
        if (lane < 8) ws[lane] = t;
    }
    __syncthreads();
    return s + ((w > 0) ? ws[w - 1] : 0);
}

__global__ void k_scan_part(const int* __restrict__ cnt, int* __restrict__ part, int n) {
    __shared__ int ws[8];
    int i = blockIdx.x * 256 + threadIdx.x;
    int v = (i < n) ? cnt[i] : 0;
    const int lane = threadIdx.x & 31, w = threadIdx.x >> 5;
#pragma unroll
    for (int o = 16; o > 0; o >>= 1) v += __shfl_xor_sync(0xFFFFFFFFu, v, o);
    if (lane == 0) ws[w] = v;
    __syncthreads();
    if (threadIdx.x == 0) {
        int s = 0;
#pragma unroll
        for (int j = 0; j < 8; j++) s += ws[j];
        part[blockIdx.x] = s;
    }
}

__global__ void k_scan_mid(int* __restrict__ part, int nb) {
    int t = threadIdx.x;
    int v = (t < nb) ? part[t] : 0;
    int incl = block_incl_scan(v, t);
    if (t < nb) part[t] = incl - v;     // exclusive
}

__global__ void k_scan_fin(const int* __restrict__ cnt, const int* __restrict__ part,
                           int* __restrict__ off, int* __restrict__ cursor, int n) {
    int i = blockIdx.x * 256 + threadIdx.x;
    int v = (i < n) ? cnt[i] : 0;
    int incl = block_incl_scan(v, threadIdx.x);
    int excl = part[blockIdx.x] + incl - v;
    if (i < n) { off[i] = excl; cursor[i] = excl; }
    if (i == n - 1) off[n] = excl + v;
}

// ---------------- CSR placement + norm precompute ----------------
__global__ void k_place(const int* __restrict__ ei, const float* __restrict__ ew,
                        const float* __restrict__ dis,
                        int* __restrict__ cursor,
                        int* __restrict__ csrc, float* __restrict__ cnrm, int e) {
    int i = blockIdx.x * blockDim.x + threadIdx.x;
    if (i >= e) return;
    int s = ei[i];
    int d = ei[e + i];
    float nrm = dis[s] * ew[i] * dis[d];
    int pos = atomicAdd(&cursor[d], 1);
    csrc[pos] = s;
    cnrm[pos] = nrm;
}

// ---------------- SGEMM (FFMA2, fragment double-buffer) ----------------
// BM=128, BN=128, BK=16, 256 threads, 8x8/thread, 2-stage smem pipeline.
__device__ __forceinline__ void tile_mac(const float (*__restrict__ As)[128],
                                         const float (*__restrict__ Bs)[128],
                                         unsigned long long acc2[8][4],
                                         int ty, int tx) {
    float4 fa0 = *(const float4*)&As[0][ty * 8];
    float4 fa1 = *(const float4*)&As[0][ty * 8 + 4];
    ulonglong2 fb0 = *(const ulonglong2*)&Bs[0][tx * 8];
    ulonglong2 fb1 = *(const ulonglong2*)&Bs[0][tx * 8 + 4];
#pragma unroll
    for (int kk = 0; kk < 16; kk++) {
        float4 na0, na1; ulonglong2 nb0, nb1;
        if (kk < 15) {
            na0 = *(const float4*)&As[kk + 1][ty * 8];
            na1 = *(const float4*)&As[kk + 1][ty * 8 + 4];
            nb0 = *(const ulonglong2*)&Bs[kk + 1][tx * 8];
            nb1 = *(const ulonglong2*)&Bs[kk + 1][tx * 8 + 4];
        }
        unsigned long long b2[4] = {fb0.x, fb0.y, fb1.x, fb1.y};
        unsigned long long a2[8] = {
            pack2(fa0.x), pack2(fa0.y), pack2(fa0.z), pack2(fa0.w),
            pack2(fa1.x), pack2(fa1.y), pack2(fa1.z), pack2(fa1.w)};
#pragma unroll
        for (int i = 0; i < 8; i++)
#pragma unroll
            for (int j = 0; j < 4; j++)
                ffma2(acc2[i][j], a2[i], b2[j]);
        fa0 = na0; fa1 = na1; fb0 = nb0; fb1 = nb1;
    }
}

__global__ __launch_bounds__(256, 2)
void k_sgemm(const float* __restrict__ A, const float* __restrict__ B,
             float* __restrict__ C, int M, int N, int K) {
    __shared__ float As[2][16][128];
    __shared__ float Bs[2][16][128];

    const int tid = threadIdx.x;
    const int tx  = tid & 15;
    const int ty  = tid >> 4;
    const int blockRow = blockIdx.y;
    const int blockCol = blockIdx.x;

    const int aRow = tid >> 2;
    const int aCol = (tid & 3) * 4;
    const int bRow = tid >> 5;
    const int bCol = (tid & 31) * 4;

    const float* Ablk = A + (size_t)blockRow * 128 * K;
    const float* Bblk = B + blockCol * 128;

    unsigned long long acc2[8][4];
#pragma unroll
    for (int i = 0; i < 8; i++)
#pragma unroll
        for (int j = 0; j < 4; j++) acc2[i][j] = 0ull;

    float4 ra[2];

#pragma unroll
    for (int r = 0; r < 2; r++) {
        int row  = aRow + r * 64;
        int grow = blockRow * 128 + row;
        ra[r] = make_float4(0.f, 0.f, 0.f, 0.f);
        if (grow < M)
            ra[r] = *(const float4*)(Ablk + (size_t)row * K + aCol);
    }
#pragma unroll
    for (int r = 0; r < 2; r++) {
        int row = bRow + r * 8;
        cp_async16(smem_u32(&Bs[0][row][bCol]), Bblk + (size_t)row * N + bCol);
    }
    CP_COMMIT();
#pragma unroll
    for (int r = 0; r < 2; r++) {
        int row = aRow + r * 64;
        As[0][aCol + 0][row] = ra[r].x;
        As[0][aCol + 1][row] = ra[r].y;
        As[0][aCol + 2][row] = ra[r].z;
        As[0][aCol + 3][row] = ra[r].w;
    }
    CP_WAIT0();
    __syncthreads();

    int buf = 0;
    for (int k0 = 16; k0 < K; k0 += 16) {
        int nbuf = buf ^ 1;
#pragma unroll
        for (int r = 0; r < 2; r++) {
            int row = bRow + r * 8;
            cp_async16(smem_u32(&Bs[nbuf][row][bCol]),
                       Bblk + (size_t)(k0 + row) * N + bCol);
        }
        CP_COMMIT();
#pragma unroll
        for (int r = 0; r < 2; r++) {
            int row  = aRow + r * 64;
            int grow = blockRow * 128 + row;
            ra[r] = make_float4(0.f, 0.f, 0.f, 0.f);
            if (grow < M)
                ra[r] = *(const float4*)(Ablk + (size_t)row * K + k0 + aCol);
        }

        tile_mac(As[buf], Bs[buf], acc2, ty, tx);

#pragma unroll
        for (int r = 0; r < 2; r++) {
            int row = aRow + r * 64;
            As[nbuf][aCol + 0][row] = ra[r].x;
            As[nbuf][aCol + 1][row] = ra[r].y;
            As[nbuf][aCol + 2][row] = ra[r].z;
            As[nbuf][aCol + 3][row] = ra[r].w;
        }
        CP_WAIT0();
        __syncthreads();
        buf = nbuf;
    }

    tile_mac(As[buf], Bs[buf], acc2, ty, tx);

    int colBase = blockCol * 128 + tx * 8;
#pragma unroll
    for (int i = 0; i < 8; i++) {
        int grow = blockRow * 128 + ty * 8 + i;
        if (grow >= M) continue;
        size_t off = (size_t)grow * N + colBase;
        float4 c0, c1;
        unpack2(acc2[i][0], c0.x, c0.y);
        unpack2(acc2[i][1], c0.z, c0.w);
        unpack2(acc2[i][2], c1.x, c1.y);
        unpack2(acc2[i][3], c1.z, c1.w);
        *(float4*)(C + off)     = c0;
        *(float4*)(C + off + 4) = c1;
    }
}

// ---------------- fused CSR aggregation + BN/ReLU or L2norm ----------------
template <int F, bool FINAL>
__global__ __launch_bounds__(256)
void k_agg(const float* __restrict__ t,
           const int* __restrict__ off, const int* __restrict__ csrc,
           const float* __restrict__ cnrm,
           const float* __restrict__ bias, const float* __restrict__ dis,
           const float* __restrict__ bg, const float* __restrict__ bb,
           const float* __restrict__ bm, const float* __restrict__ bv,
           float* __restrict__ out, int n) {
    const int row = blockIdx.x * 8 + (threadIdx.x >> 5);
    if (row >= n) return;
    const int lane = threadIdx.x & 31;
    constexpr int V = F / 128;

    float4 acc[V];
    {
        const float dvv = dis[row];
        const float d2 = dvv * dvv;
        const float4* trow = (const float4*)(t + (size_t)row * F);
#pragma unroll
        for (int j = 0; j < V; j++) {
            float4 tv = trow[lane + j * 32];
            float4 bvv = ((const float4*)bias)[lane + j * 32];
            acc[j].x = bvv.x + tv.x * d2;
            acc[j].y = bvv.y + tv.y * d2;
            acc[j].z = bvv.z + tv.z * d2;
            acc[j].w = bvv.w + tv.w * d2;
        }
    }

    int e = __ldg(&off[row]);
    const int e1 = __ldg(&off[row + 1]);
    for (; e + 1 < e1; e += 2) {
        int s0 = __ldg(&csrc[e]);
        int s1 = __ldg(&csrc[e + 1]);
        float w0 = __ldg(&cnrm[e]);
        float w1 = __ldg(&cnrm[e + 1]);
        const float4* r0 = (const float4*)(t + (size_t)s0 * F);
        const float4* r1 = (const float4*)(t + (size_t)s1 * F);
#pragma unroll
        for (int j = 0; j < V; j++) {
            float4 x0 = r0[lane + j * 32];
            float4 x1 = r1[lane + j * 32];
            acc[j].x += w0 * x0.x + w1 * x1.x;
            acc[j].y += w0 * x0.y + w1 * x1.y;
            acc[j].z += w0 * x0.z + w1 * x1.z;
            acc[j].w += w0 * x0.w + w1 * x1.w;
        }
    }
    if (e < e1) {
        int s0 = __ldg(&csrc[e]);
        float w0 = __ldg(&cnrm[e]);
        const float4* r0 = (const float4*)(t + (size_t)s0 * F);
#pragma unroll
        for (int j = 0; j < V; j++) {
            float4 x0 = r0[lane + j * 32];
            acc[j].x += w0 * x0.x;
            acc[j].y += w0 * x0.y;
            acc[j].z += w0 * x0.z;
            acc[j].w += w0 * x0.w;
        }
    }

    if (FINAL) {
        float ss = acc[0].x * acc[0].x + acc[0].y * acc[0].y
                 + acc[0].z * acc[0].z + acc[0].w * acc[0].w;
#pragma unroll
        for (int o = 16; o > 0; o >>= 1)
            ss += __shfl_xor_sync(0xFFFFFFFFu, ss, o);
        float inv = 1.0f / fmaxf(sqrtf(ss), NORM_EPS);
        float4 o4 = make_float4(acc[0].x * inv, acc[0].y * inv,
                                acc[0].z * inv, acc[0].w * inv);
        ((float4*)(out + (size_t)row * F))[lane] = o4;
    } else {
        float4* orow = (float4*)(out + (size_t)row * F);
#pragma unroll
        for (int j = 0; j < V; j++) {
            int c = lane + j * 32;
            float4 g = ((const float4*)bg)[c];
            float4 b = ((const float4*)bb)[c];
            float4 m = ((const float4*)bm)[c];
            float4 v = ((const float4*)bv)[c];
            float4 o;
            o.x = fmaxf((acc[j].x - m.x) * rsqrtf(v.x + BN_EPS) * g.x + b.x, 0.0f);
            o.y = fmaxf((acc[j].y - m.y) * rsqrtf(v.y + BN_EPS) * g.y + b.y, 0.0f);
            o.z = fmaxf((acc[j].z - m.z) * rsqrtf(v.z + BN_EPS) * g.z + b.z, 0.0f);
            o.w = fmaxf((acc[j].w - m.w) * rsqrtf(v.w + BN_EPS) * g.w + b.w, 0.0f);
            orow[c] = o;
        }
    }
}

// ---------------- launch ----------------
extern "C" void kernel_launch(void* const* d_in, const int* in_sizes, int n_in,
                              void* d_out, int out_size) {
    const float* x   = (const float*)d_in[0];
    const int*   ei  = (const int*)d_in[1];     // int32 (JAX x64 disabled)
    const float* ew  = (const float*)d_in[2];
    const float* W1  = (const float*)d_in[3];
    const float* b1  = (const float*)d_in[4];
    const float* W2  = (const float*)d_in[5];
    const float* b2  = (const float*)d_in[6];
    const float* W3  = (const float*)d_in[7];
    const float* b3  = (const float*)d_in[8];
    const float* bn1_g = (const float*)d_in[9];
    const float* bn1_b = (const float*)d_in[10];
    const float* bn1_m = (const float*)d_in[11];
    const float* bn1_v = (const float*)d_in[12];
    const float* bn2_g = (const float*)d_in[13];
    const float* bn2_b = (const float*)d_in[14];
    const float* bn2_m = (const float*)d_in[15];
    const float* bn2_v = (const float*)d_in[16];
    float* out = (float*)d_out;

    const int n = NN;
    const int e = in_sizes[2];   // 800000

    float *deg, *t, *h, *cnrm;
    int *cnt, *off, *cursor, *csrc, *part;
    cudaGetSymbolAddress((void**)&deg, g_deg);
    cudaGetSymbolAddress((void**)&t,   g_t);
    cudaGetSymbolAddress((void**)&h,   g_h);
    cudaGetSymbolAddress((void**)&cnt, g_cnt);
    cudaGetSymbolAddress((void**)&off, g_off);
    cudaGetSymbolAddress((void**)&cursor, g_cursor);
    cudaGetSymbolAddress((void**)&csrc, g_csr_src);
    cudaGetSymbolAddress((void**)&cnrm, g_csr_nrm);
    cudaGetSymbolAddress((void**)&part, g_part);

    const int TB = 256;
    const int nb = NBLK;
    // ---- graph preprocessing ----
    k_init<<<(n + TB - 1) / TB, TB>>>(deg, cnt, n);
    k_deg_cnt<<<(e + TB - 1) / TB, TB>>>(ei, ew, deg, cnt, e);
    k_rsqrt<<<(n + TB - 1) / TB, TB>>>(deg, n);
    k_scan_part<<<nb, 256>>>(cnt, part, n);
    k_scan_mid<<<1, 256>>>(part, nb);
    k_scan_fin<<<nb, 256>>>(cnt, part, off, cursor, n);
    k_place<<<(e + TB - 1) / TB, TB>>>(ei, ew, deg, cursor, csrc, cnrm, e);

    const int mBlocks = (n + 127) / 128;
    const int aBlocks = (n + 7) / 8;

    // ---- layer 1 ----
    k_sgemm<<<dim3(HID / 128, mBlocks), 256>>>(x, W1, t, n, HID, IN_DIM);
    k_agg<HID, false><<<aBlocks, 256>>>(t, off, csrc, cnrm, b1, deg,
                                        bn1_g, bn1_b, bn1_m, bn1_v, h, n);
    // ---- layer 2 ----
    k_sgemm<<<dim3(HID / 128, mBlocks), 256>>>(h, W2, t, n, HID, HID);
    k_agg<HID, false><<<aBlocks, 256>>>(t, off, csrc, cnrm, b2, deg,
                                        bn2_g, bn2_b, bn2_m, bn2_v, h, n);
    // ---- layer 3 ----
    k_sgemm<<<dim3(OUT_DIM / 128, mBlocks), 256>>>(h, W3, t, n, OUT_DIM, HID);
    k_agg<OUT_DIM, true><<<aBlocks, 256>>>(t, off, csrc, cnrm, b3, deg,
                                           nullptr, nullptr, nullptr, nullptr, out, n);
}